// round 4
// baseline (speedup 1.0000x reference)
#include <cuda_runtime.h>
#include <math.h>

// ---------------- problem constants ----------------
#define BSZ   64
#define HH    56
#define WW2   56
#define CCH   256
#define WIN   7
#define NSH   3          // shift
#define HEADS 8
#define HD    32
#define NTOK  49         // WIN*WIN
#define ROWS  200704     // BSZ*HH*WW2

// ---------------- scratch (static device arrays; no allocation) ----------------
__device__ float g_ywin[(size_t)ROWS * CCH];   // LN1 + shifted window layout; reused as LN2 output
__device__ float g_q[(size_t)ROWS * CCH];      // [win*8+head][49][32]
__device__ float g_k[(size_t)ROWS * CCH];
__device__ float g_v[(size_t)ROWS * CCH];
__device__ float g_owin[(size_t)ROWS * CCH];   // attention output, window layout
__device__ float g_x2[(size_t)ROWS * CCH];     // shortcut + proj (token layout)
__device__ float g_hid[(size_t)ROWS * 1024];   // MLP hidden

typedef unsigned long long u64;

// ---------------- f32x2 packed math ----------------
__device__ __forceinline__ u64 pack2(float x, float y) {
    u64 r; asm("mov.b64 %0, {%1, %2};" : "=l"(r) : "f"(x), "f"(y)); return r;
}
__device__ __forceinline__ void fma2(u64 &acc, u64 a, u64 b) {
    asm("fma.rn.f32x2 %0, %1, %2, %0;" : "+l"(acc) : "l"(a), "l"(b));
}
__device__ __forceinline__ float2 unpack2(u64 v) {
    float2 f; asm("mov.b64 {%0, %1}, %2;" : "=f"(f.x), "=f"(f.y) : "l"(v)); return f;
}

__device__ __forceinline__ float gelu_exact(float x) {
    return 0.5f * x * (1.0f + erff(x * 0.7071067811865476f));
}

// window-layout row -> token-layout row ( (hs+3)%56, (ws+3)%56 )
__device__ __forceinline__ size_t remap_row(int row) {
    int bimg = row / 3136;
    int rem  = row - bimg * 3136;
    int wi   = rem / NTOK;
    int p    = rem - wi * NTOK;
    int whi  = wi >> 3, wwi = wi & 7;
    int ii   = p / 7,   jj  = p - (p / 7) * 7;
    int h = whi * 7 + ii + NSH; if (h >= HH)  h -= HH;
    int w = wwi * 7 + jj + NSH; if (w >= WW2) w -= WW2;
    return (size_t)bimg * 3136 + h * WW2 + w;
}

// ---------------- LayerNorm (one warp per row). REMAP=1: read rolled token, write window layout ----------------
template<int REMAP>
__global__ __launch_bounds__(256)
void ln_kernel(const float* __restrict__ x, const float* __restrict__ gma,
               const float* __restrict__ bta, float* __restrict__ y)
{
    int orow = blockIdx.x * 8 + (threadIdx.x >> 5);
    int lane = threadIdx.x & 31;
    size_t irow = REMAP ? remap_row(orow) : (size_t)orow;
    const float* xr = x + irow * CCH;
    float4 v0 = *(const float4*)(xr + (lane << 2));
    float4 v1 = *(const float4*)(xr + 128 + (lane << 2));
    float s  = v0.x + v0.y + v0.z + v0.w + v1.x + v1.y + v1.z + v1.w;
    float sq = v0.x*v0.x + v0.y*v0.y + v0.z*v0.z + v0.w*v0.w
             + v1.x*v1.x + v1.y*v1.y + v1.z*v1.z + v1.w*v1.w;
#pragma unroll
    for (int o = 16; o > 0; o >>= 1) {
        s  += __shfl_xor_sync(0xffffffffu, s,  o);
        sq += __shfl_xor_sync(0xffffffffu, sq, o);
    }
    float mu  = s  * 0.00390625f;
    float var = sq * 0.00390625f - mu * mu;
    float inv = rsqrtf(var + 1e-5f);
    float4 g0 = *(const float4*)(gma + (lane << 2));
    float4 g1 = *(const float4*)(gma + 128 + (lane << 2));
    float4 b0 = *(const float4*)(bta + (lane << 2));
    float4 b1 = *(const float4*)(bta + 128 + (lane << 2));
    float4 o0, o1;
    o0.x = (v0.x - mu) * inv * g0.x + b0.x;
    o0.y = (v0.y - mu) * inv * g0.y + b0.y;
    o0.z = (v0.z - mu) * inv * g0.z + b0.z;
    o0.w = (v0.w - mu) * inv * g0.w + b0.w;
    o1.x = (v1.x - mu) * inv * g1.x + b1.x;
    o1.y = (v1.y - mu) * inv * g1.y + b1.y;
    o1.z = (v1.z - mu) * inv * g1.z + b1.z;
    o1.w = (v1.w - mu) * inv * g1.w + b1.w;
    float* yr = y + (size_t)orow * CCH;
    *(float4*)(yr + (lane << 2)) = o0;
    *(float4*)(yr + 128 + (lane << 2)) = o1;
}

// ---------------- GEMM 128x64x16, 256 threads, 8x4 per thread, f32x2 accum ----------------
// EPI: 0 = QKV scatter (+bias, q scale)  1 = proj (+bias, window-reverse, +x residual)
//      2 = MLP1 (+bias, exact GELU)      3 = MLP2 (+bias, +x2 residual)
template<int EPI>
__device__ __forceinline__ void epi_store(int row, int c0, float4 r, int N,
                                          const float* __restrict__ addsrc,
                                          float* __restrict__ O0,
                                          float* __restrict__ O1,
                                          float* __restrict__ O2)
{
    if (EPI == 0) {
        int win = row / NTOK;
        int n   = row - win * NTOK;
        int part = c0 >> 8;
        int cp   = c0 & 255;
        int head = cp >> 5;
        int d0   = cp & 31;
        if (part == 0) {
            const float sc = 0.17677669529663687f;   // 1/sqrt(32)
            r.x *= sc; r.y *= sc; r.z *= sc; r.w *= sc;
        }
        float* dst = (part == 0) ? O0 : ((part == 1) ? O1 : O2);
        *(float4*)&dst[((size_t)((win << 3) + head) * NTOK + n) * 32 + d0] = r;
    } else if (EPI == 1) {
        size_t drow = remap_row(row);
        float4 x4 = *(const float4*)(addsrc + drow * CCH + c0);
        r.x += x4.x; r.y += x4.y; r.z += x4.z; r.w += x4.w;
        *(float4*)(O0 + drow * CCH + c0) = r;
    } else if (EPI == 2) {
        r.x = gelu_exact(r.x); r.y = gelu_exact(r.y);
        r.z = gelu_exact(r.z); r.w = gelu_exact(r.w);
        *(float4*)(O0 + (size_t)row * N + c0) = r;
    } else {
        float4 x4 = *(const float4*)(addsrc + (size_t)row * CCH + c0);
        r.x += x4.x; r.y += x4.y; r.z += x4.z; r.w += x4.w;
        *(float4*)(O0 + (size_t)row * CCH + c0) = r;
    }
}

template<int EPI, int K, int N>
__global__ __launch_bounds__(256)
void gemm_kernel(const float* __restrict__ A, const float* __restrict__ W,
                 const float* __restrict__ bias, const float* __restrict__ addsrc,
                 float* __restrict__ O0, float* __restrict__ O1, float* __restrict__ O2)
{
    __shared__ float As[2][16][128];   // [k][m], transposed
    __shared__ float Bs[2][16][64];    // [k][n]
    const int tid = threadIdx.x;
    const int tx  = tid & 15;          // n dir (x4)
    const int ty  = tid >> 4;          // m dir (x8)
    const int m0  = blockIdx.y << 7;
    const int n0  = blockIdx.x << 6;

    const int ra = tid >> 2;           // 0..63
    const int ca = (tid & 3) << 2;     // 0,4,8,12
    const int rb = tid >> 4;           // 0..15
    const int cb = (tid & 15) << 2;    // 0..60

    const float* Ap  = A + (size_t)(m0 + ra)      * K + ca;
    const float* Ap2 = A + (size_t)(m0 + ra + 64) * K + ca;
    const float* Wp  = W + (size_t)rb * N + n0 + cb;

    float4 fa0 = *(const float4*)Ap;
    float4 fa1 = *(const float4*)Ap2;
    float4 fb  = *(const float4*)Wp;

    u64 acc2[4][4];                    // [row-pair][col]: rows (2p,2p+1)
#pragma unroll
    for (int p = 0; p < 4; p++)
#pragma unroll
        for (int c = 0; c < 4; c++) acc2[p][c] = 0ull;

    constexpr int nk = K >> 4;
    int buf = 0;
#pragma unroll 2
    for (int kt = 0; kt < nk; ++kt) {
        As[buf][ca    ][ra]      = fa0.x;
        As[buf][ca + 1][ra]      = fa0.y;
        As[buf][ca + 2][ra]      = fa0.z;
        As[buf][ca + 3][ra]      = fa0.w;
        As[buf][ca    ][ra + 64] = fa1.x;
        As[buf][ca + 1][ra + 64] = fa1.y;
        As[buf][ca + 2][ra + 64] = fa1.z;
        As[buf][ca + 3][ra + 64] = fa1.w;
        *(float4*)&Bs[buf][rb][cb] = fb;
        __syncthreads();
        if (kt + 1 < nk) {
            fa0 = *(const float4*)(Ap  + (kt + 1) * 16);
            fa1 = *(const float4*)(Ap2 + (kt + 1) * 16);
            fb  = *(const float4*)(Wp  + (size_t)(kt + 1) * 16 * N);
        }
#pragma unroll
        for (int kk = 0; kk < 16; ++kk) {
            float4 a0 = *(const float4*)&As[buf][kk][ty << 3];
            float4 a1 = *(const float4*)&As[buf][kk][(ty << 3) + 4];
            float4 b4 = *(const float4*)&Bs[buf][kk][tx << 2];
            u64 ap[4], bd[4];
            ap[0] = pack2(a0.x, a0.y); ap[1] = pack2(a0.z, a0.w);
            ap[2] = pack2(a1.x, a1.y); ap[3] = pack2(a1.z, a1.w);
            bd[0] = pack2(b4.x, b4.x); bd[1] = pack2(b4.y, b4.y);
            bd[2] = pack2(b4.z, b4.z); bd[3] = pack2(b4.w, b4.w);
#pragma unroll
            for (int p = 0; p < 4; p++)
#pragma unroll
                for (int c = 0; c < 4; c++)
                    fma2(acc2[p][c], ap[p], bd[c]);
        }
        buf ^= 1;
    }

    const int c0 = n0 + (tx << 2);
    const float4 bs4 = *(const float4*)(bias + c0);
#pragma unroll
    for (int p = 0; p < 4; p++) {
        float2 rc0 = unpack2(acc2[p][0]);
        float2 rc1 = unpack2(acc2[p][1]);
        float2 rc2 = unpack2(acc2[p][2]);
        float2 rc3 = unpack2(acc2[p][3]);
        int row0 = m0 + (ty << 3) + (p << 1);
        float4 r0 = make_float4(rc0.x + bs4.x, rc1.x + bs4.y, rc2.x + bs4.z, rc3.x + bs4.w);
        float4 r1 = make_float4(rc0.y + bs4.x, rc1.y + bs4.y, rc2.y + bs4.z, rc3.y + bs4.w);
        epi_store<EPI>(row0,     c0, r0, N, addsrc, O0, O1, O2);
        epi_store<EPI>(row0 + 1, c0, r1, N, addsrc, O0, O1, O2);
    }
}

// ---------------- attention: one block per (window, head) ----------------
__global__ __launch_bounds__(256)
void attn_kernel(const float* __restrict__ q, const float* __restrict__ k,
                 const float* __restrict__ v, const float* __restrict__ rpb,
                 float* __restrict__ o)
{
    __shared__ float qt[32][52];       // transposed q [d][n], padded
    __shared__ float kt[32][52];
    __shared__ float vs[49][32];
    __shared__ float S[52][52];
    const int wh   = blockIdx.x;       // win*8 + head
    const int win  = wh >> 3;
    const int head = wh & 7;
    const int wimg = win & 63;
    const int whi  = wimg >> 3, wwi = wimg & 7;
    const int t    = threadIdx.x;
    const size_t base = (size_t)wh * (NTOK * HD);

    for (int idx = t; idx < NTOK * HD; idx += 256) {
        int n = idx >> 5, d = idx & 31;
        qt[d][n] = q[base + idx];
        kt[d][n] = k[base + idx];
        vs[n][d] = v[base + idx];
    }
    if (t < 32) {
        qt[t][49] = 0.f; qt[t][50] = 0.f; qt[t][51] = 0.f;
        kt[t][49] = 0.f; kt[t][50] = 0.f; kt[t][51] = 0.f;
    }
    __syncthreads();

    // S = q k^T (+bias +mask): 13x13 tiles of 4x4
    if (t < 169) {
        const int ti = t / 13, tj = t - (t / 13) * 13;
        const int i0 = ti << 2, j0 = tj << 2;
        float acc[4][4];
#pragma unroll
        for (int r = 0; r < 4; r++)
#pragma unroll
            for (int c = 0; c < 4; c++) acc[r][c] = 0.f;
#pragma unroll 8
        for (int d = 0; d < 32; d++) {
            float4 qa = *(const float4*)&qt[d][i0];
            float4 kb = *(const float4*)&kt[d][j0];
            float av[4] = {qa.x, qa.y, qa.z, qa.w};
            float bv[4] = {kb.x, kb.y, kb.z, kb.w};
#pragma unroll
            for (int r = 0; r < 4; r++)
#pragma unroll
                for (int c = 0; c < 4; c++)
                    acc[r][c] = fmaf(av[r], bv[c], acc[r][c]);
        }
#pragma unroll
        for (int r = 0; r < 4; r++) {
            int i = i0 + r;
            if (i < NTOK) {
                int ri = i / 7, ci = i - ri * 7;
                int hhp = whi * 7 + ri;
                int wwp = wwi * 7 + ci;
                int regi = ((hhp < 49) ? 0 : ((hhp < 53) ? 1 : 2)) * 3
                         + ((wwp < 49) ? 0 : ((wwp < 53) ? 1 : 2));
#pragma unroll
                for (int c = 0; c < 4; c++) {
                    int j = j0 + c;
                    float val;
                    if (j < NTOK) {
                        int rj = j / 7, cj = j - rj * 7;
                        float bias = rpb[((ri - rj + 6) * 13 + (ci - cj + 6)) * HEADS + head];
                        int hhq = whi * 7 + rj;
                        int wwq = wwi * 7 + cj;
                        int regj = ((hhq < 49) ? 0 : ((hhq < 53) ? 1 : 2)) * 3
                                 + ((wwq < 49) ? 0 : ((wwq < 53) ? 1 : 2));
                        val = acc[r][c] + bias + ((regi == regj) ? 0.f : -100.f);
                    } else {
                        val = -1e30f;
                    }
                    S[i][j] = val;
                }
            }
        }
    }
    __syncthreads();

    // softmax: one thread per row
    if (t < NTOK) {
        float mx = -1e30f;
#pragma unroll
        for (int j = 0; j < NTOK; j++) mx = fmaxf(mx, S[t][j]);
        float s = 0.f;
#pragma unroll
        for (int j = 0; j < NTOK; j++) {
            float e = __expf(S[t][j] - mx);
            S[t][j] = e; s += e;
        }
        float inv = 1.f / s;
#pragma unroll
        for (int j = 0; j < NTOK; j++) S[t][j] *= inv;
    }
    __syncthreads();

    // O = P @ V: 13x8 tiles of 4x4 (rows x dims)
    if (t < 104) {
        const int ti = t >> 3, td = t & 7;
        const int i0 = ti << 2, d0 = td << 2;
        float acc[4][4];
#pragma unroll
        for (int r = 0; r < 4; r++)
#pragma unroll
            for (int c = 0; c < 4; c++) acc[r][c] = 0.f;
#pragma unroll 7
        for (int j = 0; j < NTOK; j++) {
            float4 v4 = *(const float4*)&vs[j][d0];
#pragma unroll
            for (int r = 0; r < 4; r++) {
                float p = S[i0 + r][j];   // rows 49..51 hold garbage but are discarded
                acc[r][0] = fmaf(p, v4.x, acc[r][0]);
                acc[r][1] = fmaf(p, v4.y, acc[r][1]);
                acc[r][2] = fmaf(p, v4.z, acc[r][2]);
                acc[r][3] = fmaf(p, v4.w, acc[r][3]);
            }
        }
#pragma unroll
        for (int r = 0; r < 4; r++) {
            int i = i0 + r;
            if (i < NTOK) {
                float4 rr = make_float4(acc[r][0], acc[r][1], acc[r][2], acc[r][3]);
                *(float4*)&o[((size_t)(win * NTOK + i)) * CCH + head * HD + d0] = rr;
            }
        }
    }
}

// ---------------- launch ----------------
extern "C" void kernel_launch(void* const* d_in, const int* in_sizes, int n_in,
                              void* d_out, int out_size)
{
    const float* x      = (const float*)d_in[0];
    const float* ln1_g  = (const float*)d_in[1];
    const float* ln1_b  = (const float*)d_in[2];
    const float* qkv_w  = (const float*)d_in[3];
    const float* qkv_b  = (const float*)d_in[4];
    const float* rpb    = (const float*)d_in[5];
    const float* proj_w = (const float*)d_in[6];
    const float* proj_b = (const float*)d_in[7];
    const float* ln2_g  = (const float*)d_in[8];
    const float* ln2_b  = (const float*)d_in[9];
    const float* mlp_w1 = (const float*)d_in[10];
    const float* mlp_b1 = (const float*)d_in[11];
    const float* mlp_w2 = (const float*)d_in[12];
    const float* mlp_b2 = (const float*)d_in[13];

    float *ywin, *qb, *kb, *vb, *owin, *x2, *hid;
    cudaGetSymbolAddress((void**)&ywin, g_ywin);
    cudaGetSymbolAddress((void**)&qb,   g_q);
    cudaGetSymbolAddress((void**)&kb,   g_k);
    cudaGetSymbolAddress((void**)&vb,   g_v);
    cudaGetSymbolAddress((void**)&owin, g_owin);
    cudaGetSymbolAddress((void**)&x2,   g_x2);
    cudaGetSymbolAddress((void**)&hid,  g_hid);

    // 1) LN1 + roll + window partition
    ln_kernel<1><<<ROWS / 8, 256>>>(x, ln1_g, ln1_b, ywin);
    // 2) QKV GEMM (scatter to q/k/v per-head layout, q scaled)
    gemm_kernel<0, 256, 768><<<dim3(768 / 64, ROWS / 128), 256>>>(ywin, qkv_w, qkv_b, nullptr,
                                                                  qb, kb, vb);
    // 3) windowed attention
    attn_kernel<<<4096 * 8, 256>>>(qb, kb, vb, rpb, owin);
    // 4) proj GEMM + window reverse + un-shift + residual -> x2
    gemm_kernel<1, 256, 256><<<dim3(256 / 64, ROWS / 128), 256>>>(owin, proj_w, proj_b, x,
                                                                  x2, nullptr, nullptr);
    // 5) LN2
    ln_kernel<0><<<ROWS / 8, 256>>>(x2, ln2_g, ln2_b, ywin);
    // 6) MLP1 + GELU
    gemm_kernel<2, 256, 1024><<<dim3(1024 / 64, ROWS / 128), 256>>>(ywin, mlp_w1, mlp_b1, nullptr,
                                                                    hid, nullptr, nullptr);
    // 7) MLP2 + residual -> out
    gemm_kernel<3, 1024, 256><<<dim3(256 / 64, ROWS / 128), 256>>>(hid, mlp_w2, mlp_b2, x2,
                                                                   (float*)d_out, nullptr, nullptr);
    (void)in_sizes; (void)n_in; (void)out_size;
}

// round 8
// speedup vs baseline: 1.5275x; 1.5275x over previous
#include <cuda_runtime.h>
#include <cuda_bf16.h>
#include <math.h>
#include <stdint.h>

// ---------------- problem constants ----------------
#define BSZ   64
#define HH    56
#define WW2   56
#define CCH   256
#define WIN   7
#define NSH   3
#define HEADS 8
#define HD    32
#define NTOK  49
#define ROWS  200704     // BSZ*HH*WW2

typedef unsigned long long u64;
typedef __nv_bfloat16 bf16;

// ---------------- scratch (static device arrays; no allocation) ----------------
__device__ __align__(16) bf16 g_ywh[(size_t)ROWS * CCH];   // LN out hi
__device__ __align__(16) bf16 g_ywl[(size_t)ROWS * CCH];   // LN out lo
__device__ __align__(16) float g_q[(size_t)ROWS * CCH];    // [win*8+head][49][32]
__device__ __align__(16) float g_k[(size_t)ROWS * CCH];
__device__ __align__(16) float g_v[(size_t)ROWS * CCH];
__device__ __align__(16) bf16 g_owh[(size_t)ROWS * CCH];   // attn out hi (window layout)
__device__ __align__(16) bf16 g_owl[(size_t)ROWS * CCH];
__device__ __align__(16) float g_x2[(size_t)ROWS * CCH];   // shortcut + proj (token layout)
__device__ __align__(16) bf16 g_hh[(size_t)ROWS * 1024];   // GELU hidden hi
__device__ __align__(16) bf16 g_hl[(size_t)ROWS * 1024];
// transposed + split weights  [N][K]
__device__ __align__(16) bf16 g_wqh[768 * 256],  g_wql[768 * 256];
__device__ __align__(16) bf16 g_wph[256 * 256],  g_wpl[256 * 256];
__device__ __align__(16) bf16 g_w1h[1024 * 256], g_w1l[1024 * 256];
__device__ __align__(16) bf16 g_w2h[256 * 1024], g_w2l[256 * 1024];

// ---------------- PTX helpers (all plain sm_80+ features) ----------------
__device__ __forceinline__ uint32_t smem_u32(const void* p) {
    uint32_t a;
    asm("{ .reg .u64 t; cvta.to.shared.u64 t, %1; cvt.u32.u64 %0, t; }" : "=r"(a) : "l"(p));
    return a;
}
__device__ __forceinline__ void ldsm4(uint32_t r[4], uint32_t addr) {
    asm volatile("ldmatrix.sync.aligned.m8n8.x4.shared.b16 {%0,%1,%2,%3}, [%4];"
        : "=r"(r[0]), "=r"(r[1]), "=r"(r[2]), "=r"(r[3]) : "r"(addr));
}
__device__ __forceinline__ void mma_bf16(float acc[4], const uint32_t a[4],
                                         uint32_t b0, uint32_t b1) {
    asm volatile("mma.sync.aligned.m16n8k16.row.col.f32.bf16.bf16.f32 "
        "{%0,%1,%2,%3}, {%4,%5,%6,%7}, {%8,%9}, {%0,%1,%2,%3};"
        : "+f"(acc[0]), "+f"(acc[1]), "+f"(acc[2]), "+f"(acc[3])
        : "r"(a[0]), "r"(a[1]), "r"(a[2]), "r"(a[3]), "r"(b0), "r"(b1));
}
#define CP_ASYNC(dst, src) \
    asm volatile("cp.async.cg.shared.global [%0], [%1], 16;" :: "r"(dst), "l"(src))
#define CP_COMMIT() asm volatile("cp.async.commit_group;" ::: "memory")
#define CP_WAIT1()  asm volatile("cp.async.wait_group 1;" ::: "memory")
#define CP_WAIT0()  asm volatile("cp.async.wait_group 0;" ::: "memory")

// ---------------- misc helpers ----------------
__device__ __forceinline__ float gelu_exact(float x) {
    return 0.5f * x * (1.0f + erff(x * 0.7071067811865476f));
}
__device__ __forceinline__ size_t remap_row(int row) {
    int bimg = row / 3136;
    int rem  = row - bimg * 3136;
    int wi   = rem / NTOK;
    int p    = rem - wi * NTOK;
    int whi  = wi >> 3, wwi = wi & 7;
    int ii   = p / 7,   jj  = p - (p / 7) * 7;
    int h = whi * 7 + ii + NSH; if (h >= HH)  h -= HH;
    int w = wwi * 7 + jj + NSH; if (w >= WW2) w -= WW2;
    return (size_t)bimg * 3136 + h * WW2 + w;
}
__device__ __forceinline__ void split_store4(bf16* ph, bf16* pl, size_t off, float4 v) {
    __nv_bfloat162 h0 = __floats2bfloat162_rn(v.x, v.y);
    __nv_bfloat162 h1 = __floats2bfloat162_rn(v.z, v.w);
    float lx = v.x - __bfloat162float(h0.x);
    float ly = v.y - __bfloat162float(h0.y);
    float lz = v.z - __bfloat162float(h1.x);
    float lw = v.w - __bfloat162float(h1.y);
    __nv_bfloat162 l0 = __floats2bfloat162_rn(lx, ly);
    __nv_bfloat162 l1 = __floats2bfloat162_rn(lz, lw);
    *(__nv_bfloat162*)(ph + off)     = h0;
    *(__nv_bfloat162*)(ph + off + 2) = h1;
    *(__nv_bfloat162*)(pl + off)     = l0;
    *(__nv_bfloat162*)(pl + off + 2) = l1;
}

// ---------------- weight prep: W[K][N] fp32 -> Wt_hi/Wt_lo [N][K] bf16 ----------------
__global__ __launch_bounds__(256)
void wprep_kernel(const float* __restrict__ W, bf16* __restrict__ th,
                  bf16* __restrict__ tl, int K, int N)
{
    int idx = blockIdx.x * 256 + threadIdx.x;
    if (idx >= K * N) return;
    int k = idx / N, n = idx - k * N;
    float w = W[idx];
    bf16 h = __float2bfloat16(w);
    float lo = w - __bfloat162float(h);
    th[(size_t)n * K + k] = h;
    tl[(size_t)n * K + k] = __float2bfloat16(lo);
}

// ---------------- LayerNorm -> bf16 hi/lo.  REMAP=1: rolled gather to window layout ----------------
template<int REMAP>
__global__ __launch_bounds__(256)
void ln_kernel(const float* __restrict__ x, const float* __restrict__ gma,
               const float* __restrict__ bta, bf16* __restrict__ yh,
               bf16* __restrict__ yl)
{
    int orow = blockIdx.x * 8 + (threadIdx.x >> 5);
    int lane = threadIdx.x & 31;
    size_t irow = REMAP ? remap_row(orow) : (size_t)orow;
    const float* xr = x + irow * CCH;
    float4 v0 = *(const float4*)(xr + (lane << 2));
    float4 v1 = *(const float4*)(xr + 128 + (lane << 2));
    float s  = v0.x + v0.y + v0.z + v0.w + v1.x + v1.y + v1.z + v1.w;
    float sq = v0.x*v0.x + v0.y*v0.y + v0.z*v0.z + v0.w*v0.w
             + v1.x*v1.x + v1.y*v1.y + v1.z*v1.z + v1.w*v1.w;
#pragma unroll
    for (int o = 16; o > 0; o >>= 1) {
        s  += __shfl_xor_sync(0xffffffffu, s,  o);
        sq += __shfl_xor_sync(0xffffffffu, sq, o);
    }
    float mu  = s  * 0.00390625f;
    float var = sq * 0.00390625f - mu * mu;
    float inv = rsqrtf(var + 1e-5f);
    float4 g0 = *(const float4*)(gma + (lane << 2));
    float4 g1 = *(const float4*)(gma + 128 + (lane << 2));
    float4 b0 = *(const float4*)(bta + (lane << 2));
    float4 b1 = *(const float4*)(bta + 128 + (lane << 2));
    float4 o0, o1;
    o0.x = (v0.x - mu) * inv * g0.x + b0.x;
    o0.y = (v0.y - mu) * inv * g0.y + b0.y;
    o0.z = (v0.z - mu) * inv * g0.z + b0.z;
    o0.w = (v0.w - mu) * inv * g0.w + b0.w;
    o1.x = (v1.x - mu) * inv * g1.x + b1.x;
    o1.y = (v1.y - mu) * inv * g1.y + b1.y;
    o1.z = (v1.z - mu) * inv * g1.z + b1.z;
    o1.w = (v1.w - mu) * inv * g1.w + b1.w;
    size_t base = (size_t)orow * CCH;
    split_store4(yh, yl, base + (lane << 2), o0);
    split_store4(yh, yl, base + 128 + (lane << 2), o1);
}

// ---------------- HMMA GEMM: block 128x64, warp 32x32, K-chunk 32, hi/lo 3-pass ----------------
// smem per buffer: A hi 128x80B, A lo, B hi 64x80B, B lo
#define APITCH 80
#define SA_HI  0
#define SA_LO  10240
#define SB_HI  20480
#define SB_LO  25600
#define BUFSZ  30720
#define GSMEM  61440
#define EPITCH 68        // epilogue float pitch

// EPI: 0 = QKV scatter (+bias, q scale)  1 = proj (+bias, window-reverse, +x residual)
//      2 = MLP1 (+bias, GELU -> bf16 hi/lo)  3 = MLP2 (+bias, +x2 residual)
template<int EPI, int K, int N>
__global__ __launch_bounds__(256, 2)
void hgemm(const bf16* __restrict__ Ah, const bf16* __restrict__ Al,
           const bf16* __restrict__ Bh, const bf16* __restrict__ Bl,
           const float* __restrict__ bias, const float* __restrict__ addsrc,
           float* __restrict__ O0, float* __restrict__ O1, float* __restrict__ O2,
           bf16* __restrict__ P0, bf16* __restrict__ P1)
{
    extern __shared__ char smem[];
    const uint32_t sb = smem_u32(smem);
    const int tid  = threadIdx.x;
    const int wid  = tid >> 5;
    const int lane = tid & 31;
    const int wm   = wid >> 1;          // warp m index (0..3)
    const int wn   = wid & 1;           // warp n index (0..1)
    const int m0   = blockIdx.y << 7;
    const int n0   = blockIdx.x << 6;

    // cp.async load of one 32-K chunk into buffer b
    auto LOAD = [&](int ch, int b) {
        const size_t kc0 = (size_t)ch * 32;
        const uint32_t db = sb + b * BUFSZ;
#pragma unroll
        for (int j = 0; j < 2; j++) {
            int g = tid + 256 * j;              // 512 granules of 16B for A
            int row = g >> 2, seg = g & 3;
            size_t go = (size_t)(m0 + row) * K + kc0 + seg * 8;
            CP_ASYNC(db + SA_HI + row * APITCH + seg * 16, Ah + go);
            CP_ASYNC(db + SA_LO + row * APITCH + seg * 16, Al + go);
        }
        {
            int row = tid >> 2, seg = tid & 3;  // 256 granules for B
            size_t go = (size_t)(n0 + row) * K + kc0 + seg * 8;
            CP_ASYNC(db + SB_HI + row * APITCH + seg * 16, Bh + go);
            CP_ASYNC(db + SB_LO + row * APITCH + seg * 16, Bl + go);
        }
        CP_COMMIT();
    };

    // ldmatrix per-thread base offsets
    const int q  = lane >> 3, lr = lane & 7;
    const uint32_t aBase = (uint32_t)(wm * 32 + (q & 1) * 8 + lr) * APITCH + (q >> 1) * 16;
    const uint32_t bBase = (uint32_t)(wn * 32 + (q >> 1) * 8 + lr) * APITCH + (q & 1) * 16;

    float acc[2][4][4];
#pragma unroll
    for (int mt = 0; mt < 2; mt++)
#pragma unroll
        for (int nt = 0; nt < 4; nt++)
#pragma unroll
            for (int r = 0; r < 4; r++) acc[mt][nt][r] = 0.f;

    constexpr int NCH = K / 32;
    LOAD(0, 0);
    LOAD(1, 1);
    int buf = 0;
    for (int i = 0; i < NCH; i++) {
        if (i + 1 < NCH) { CP_WAIT1(); } else { CP_WAIT0(); }
        __syncthreads();
        const uint32_t bb = sb + buf * BUFSZ;
#pragma unroll
        for (int ks = 0; ks < 2; ks++) {
            uint32_t ah[2][4], al[2][4], bh[2][4], bl[2][4];
#pragma unroll
            for (int mt = 0; mt < 2; mt++) {
                ldsm4(ah[mt], bb + SA_HI + aBase + mt * 1280 + ks * 32);
                ldsm4(al[mt], bb + SA_LO + aBase + mt * 1280 + ks * 32);
            }
#pragma unroll
            for (int g = 0; g < 2; g++) {
                ldsm4(bh[g], bb + SB_HI + bBase + g * 1280 + ks * 32);
                ldsm4(bl[g], bb + SB_LO + bBase + g * 1280 + ks * 32);
            }
#pragma unroll
            for (int mt = 0; mt < 2; mt++) {
#pragma unroll
                for (int g = 0; g < 2; g++) {
                    mma_bf16(acc[mt][2 * g],     ah[mt], bh[g][0], bh[g][1]);
                    mma_bf16(acc[mt][2 * g],     ah[mt], bl[g][0], bl[g][1]);
                    mma_bf16(acc[mt][2 * g],     al[mt], bh[g][0], bh[g][1]);
                    mma_bf16(acc[mt][2 * g + 1], ah[mt], bh[g][2], bh[g][3]);
                    mma_bf16(acc[mt][2 * g + 1], ah[mt], bl[g][2], bl[g][3]);
                    mma_bf16(acc[mt][2 * g + 1], al[mt], bh[g][2], bh[g][3]);
                }
            }
        }
        __syncthreads();
        if (i + 2 < NCH) LOAD(i + 2, buf);
        buf ^= 1;
    }

    // ---- epilogue: stage accumulators through smem, then fused row-wise stores ----
    float* esm = (float*)smem;
    const int gid = lane >> 2, tig = lane & 3;
#pragma unroll
    for (int mt = 0; mt < 2; mt++)
#pragma unroll
        for (int nt = 0; nt < 4; nt++) {
            int r0 = wm * 32 + mt * 16 + gid;
            int cb = wn * 32 + nt * 8 + tig * 2;
            *(float2*)&esm[r0 * EPITCH + cb]       = make_float2(acc[mt][nt][0], acc[mt][nt][1]);
            *(float2*)&esm[(r0 + 8) * EPITCH + cb] = make_float2(acc[mt][nt][2], acc[mt][nt][3]);
        }
    __syncthreads();

    const int lrow = tid >> 1;
    const int chalf = (tid & 1) * 32;
    const int row = m0 + lrow;
    if (EPI == 0) {
        const int win = row / NTOK;
        const int n   = row - win * NTOK;
        const float sc = 0.17677669529663687f;   // 1/sqrt(32)
#pragma unroll
        for (int cc = 0; cc < 8; cc++) {
            const int lc = chalf + cc * 4;
            const int col = n0 + lc;
            float4 b4 = *(const float4*)(bias + col);
            float4 a4 = *(const float4*)&esm[lrow * EPITCH + lc];
            float4 v = make_float4(a4.x + b4.x, a4.y + b4.y, a4.z + b4.z, a4.w + b4.w);
            const int part = col >> 8;
            const int head = (col >> 5) & 7;
            const int d0   = col & 31;
            if (part == 0) { v.x *= sc; v.y *= sc; v.z *= sc; v.w *= sc; }
            float* dst = (part == 0) ? O0 : ((part == 1) ? O1 : O2);
            *(float4*)&dst[((size_t)((win << 3) + head) * NTOK + n) * 32 + d0] = v;
        }
    } else if (EPI == 1) {
        const size_t dr = remap_row(row);
#pragma unroll
        for (int cc = 0; cc < 8; cc++) {
            const int lc = chalf + cc * 4;
            const int col = n0 + lc;
            float4 b4 = *(const float4*)(bias + col);
            float4 x4 = *(const float4*)(addsrc + dr * CCH + col);
            float4 a4 = *(const float4*)&esm[lrow * EPITCH + lc];
            float4 v = make_float4(a4.x + b4.x + x4.x, a4.y + b4.y + x4.y,
                                   a4.z + b4.z + x4.z, a4.w + b4.w + x4.w);
            *(float4*)(O0 + dr * CCH + col) = v;
        }
    } else if (EPI == 2) {
#pragma unroll
        for (int cc = 0; cc < 8; cc++) {
            const int lc = chalf + cc * 4;
            const int col = n0 + lc;
            float4 b4 = *(const float4*)(bias + col);
            float4 a4 = *(const float4*)&esm[lrow * EPITCH + lc];
            float4 v = make_float4(gelu_exact(a4.x + b4.x), gelu_exact(a4.y + b4.y),
                                   gelu_exact(a4.z + b4.z), gelu_exact(a4.w + b4.w));
            split_store4(P0, P1, (size_t)row * N + col, v);
        }
    } else {
#pragma unroll
        for (int cc = 0; cc < 8; cc++) {
            const int lc = chalf + cc * 4;
            const int col = n0 + lc;
            float4 b4 = *(const float4*)(bias + col);
            float4 x4 = *(const float4*)(addsrc + (size_t)row * CCH + col);
            float4 a4 = *(const float4*)&esm[lrow * EPITCH + lc];
            float4 v = make_float4(a4.x + b4.x + x4.x, a4.y + b4.y + x4.y,
                                   a4.z + b4.z + x4.z, a4.w + b4.w + x4.w);
            *(float4*)(O0 + (size_t)row * CCH + col) = v;
        }
    }
}

// ---------------- attention: one block per (window, head); outputs bf16 hi/lo ----------------
__global__ __launch_bounds__(256)
void attn_kernel(const float* __restrict__ q, const float* __restrict__ k,
                 const float* __restrict__ v, const float* __restrict__ rpb,
                 bf16* __restrict__ oh, bf16* __restrict__ ol)
{
    __shared__ float qt[32][52];
    __shared__ float kt[32][52];
    __shared__ float vs[49][32];
    __shared__ float S[52][52];
    const int wh   = blockIdx.x;
    const int win  = wh >> 3;
    const int head = wh & 7;
    const int wimg = win & 63;
    const int whi  = wimg >> 3, wwi = wimg & 7;
    const int t    = threadIdx.x;
    const size_t base = (size_t)wh * (NTOK * HD);

    for (int idx = t; idx < NTOK * HD; idx += 256) {
        int n = idx >> 5, d = idx & 31;
        qt[d][n] = q[base + idx];
        kt[d][n] = k[base + idx];
        vs[n][d] = v[base + idx];
    }
    if (t < 32) {
        qt[t][49] = 0.f; qt[t][50] = 0.f; qt[t][51] = 0.f;
        kt[t][49] = 0.f; kt[t][50] = 0.f; kt[t][51] = 0.f;
    }
    __syncthreads();

    if (t < 169) {
        const int ti = t / 13, tj = t - (t / 13) * 13;
        const int i0 = ti << 2, j0 = tj << 2;
        float acc[4][4];
#pragma unroll
        for (int r = 0; r < 4; r++)
#pragma unroll
            for (int c = 0; c < 4; c++) acc[r][c] = 0.f;
#pragma unroll 8
        for (int d = 0; d < 32; d++) {
            float4 qa = *(const float4*)&qt[d][i0];
            float4 kb = *(const float4*)&kt[d][j0];
            float av[4] = {qa.x, qa.y, qa.z, qa.w};
            float bv[4] = {kb.x, kb.y, kb.z, kb.w};
#pragma unroll
            for (int r = 0; r < 4; r++)
#pragma unroll
                for (int c = 0; c < 4; c++)
                    acc[r][c] = fmaf(av[r], bv[c], acc[r][c]);
        }
#pragma unroll
        for (int r = 0; r < 4; r++) {
            int i = i0 + r;
            if (i < NTOK) {
                int ri = i / 7, ci = i - ri * 7;
                int hhp = whi * 7 + ri;
                int wwp = wwi * 7 + ci;
                int regi = ((hhp < 49) ? 0 : ((hhp < 53) ? 1 : 2)) * 3
                         + ((wwp < 49) ? 0 : ((wwp < 53) ? 1 : 2));
#pragma unroll
                for (int c = 0; c < 4; c++) {
                    int j = j0 + c;
                    float val;
                    if (j < NTOK) {
                        int rj = j / 7, cj = j - rj * 7;
                        float bias = rpb[((ri - rj + 6) * 13 + (ci - cj + 6)) * HEADS + head];
                        int hhq = whi * 7 + rj;
                        int wwq = wwi * 7 + cj;
                        int regj = ((hhq < 49) ? 0 : ((hhq < 53) ? 1 : 2)) * 3
                                 + ((wwq < 49) ? 0 : ((wwq < 53) ? 1 : 2));
                        val = acc[r][c] + bias + ((regi == regj) ? 0.f : -100.f);
                    } else {
                        val = -1e30f;
                    }
                    S[i][j] = val;
                }
            }
        }
    }
    __syncthreads();

    if (t < NTOK) {
        float mx = -1e30f;
#pragma unroll
        for (int j = 0; j < NTOK; j++) mx = fmaxf(mx, S[t][j]);
        float s = 0.f;
#pragma unroll
        for (int j = 0; j < NTOK; j++) {
            float e = __expf(S[t][j] - mx);
            S[t][j] = e; s += e;
        }
        float inv = 1.f / s;
#pragma unroll
        for (int j = 0; j < NTOK; j++) S[t][j] *= inv;
    }
    __syncthreads();

    if (t < 104) {
        const int ti = t >> 3, td = t & 7;
        const int i0 = ti << 2, d0 = td << 2;
        float acc[4][4];
#pragma unroll
        for (int r = 0; r < 4; r++)
#pragma unroll
            for (int c = 0; c < 4; c++) acc[r][c] = 0.f;
#pragma unroll 7
        for (int j = 0; j < NTOK; j++) {
            float4 v4 = *(const float4*)&vs[j][d0];
#pragma unroll
            for (int r = 0; r < 4; r++) {
                float p = S[i0 + r][j];
                acc[r][0] = fmaf(p, v4.x, acc[r][0]);
                acc[r][1] = fmaf(p, v4.y, acc[r][1]);
                acc[r][2] = fmaf(p, v4.z, acc[r][2]);
                acc[r][3] = fmaf(p, v4.w, acc[r][3]);
            }
        }
#pragma unroll
        for (int r = 0; r < 4; r++) {
            int i = i0 + r;
            if (i < NTOK) {
                float4 rr = make_float4(acc[r][0], acc[r][1], acc[r][2], acc[r][3]);
                split_store4(oh, ol,
                             ((size_t)(win * NTOK + i)) * CCH + head * HD + d0, rr);
            }
        }
    }
}

// ---------------- launch ----------------
extern "C" void kernel_launch(void* const* d_in, const int* in_sizes, int n_in,
                              void* d_out, int out_size)
{
    const float* x      = (const float*)d_in[0];
    const float* ln1_g  = (const float*)d_in[1];
    const float* ln1_b  = (const float*)d_in[2];
    const float* qkv_w  = (const float*)d_in[3];
    const float* qkv_b  = (const float*)d_in[4];
    const float* rpb    = (const float*)d_in[5];
    const float* proj_w = (const float*)d_in[6];
    const float* proj_b = (const float*)d_in[7];
    const float* ln2_g  = (const float*)d_in[8];
    const float* ln2_b  = (const float*)d_in[9];
    const float* mlp_w1 = (const float*)d_in[10];
    const float* mlp_b1 = (const float*)d_in[11];
    const float* mlp_w2 = (const float*)d_in[12];
    const float* mlp_b2 = (const float*)d_in[13];

    bf16 *ywh, *ywl, *owh, *owl, *hh, *hl;
    bf16 *wqh, *wql, *wph, *wpl, *w1h, *w1l, *w2h, *w2l;
    float *qb, *kb, *vb, *x2;
    cudaGetSymbolAddress((void**)&ywh, g_ywh);
    cudaGetSymbolAddress((void**)&ywl, g_ywl);
    cudaGetSymbolAddress((void**)&qb,  g_q);
    cudaGetSymbolAddress((void**)&kb,  g_k);
    cudaGetSymbolAddress((void**)&vb,  g_v);
    cudaGetSymbolAddress((void**)&owh, g_owh);
    cudaGetSymbolAddress((void**)&owl, g_owl);
    cudaGetSymbolAddress((void**)&x2,  g_x2);
    cudaGetSymbolAddress((void**)&hh,  g_hh);
    cudaGetSymbolAddress((void**)&hl,  g_hl);
    cudaGetSymbolAddress((void**)&wqh, g_wqh);
    cudaGetSymbolAddress((void**)&wql, g_wql);
    cudaGetSymbolAddress((void**)&wph, g_wph);
    cudaGetSymbolAddress((void**)&wpl, g_wpl);
    cudaGetSymbolAddress((void**)&w1h, g_w1h);
    cudaGetSymbolAddress((void**)&w1l, g_w1l);
    cudaGetSymbolAddress((void**)&w2h, g_w2h);
    cudaGetSymbolAddress((void**)&w2l, g_w2l);

    cudaFuncSetAttribute(hgemm<0, 256, 768>,  cudaFuncAttributeMaxDynamicSharedMemorySize, GSMEM);
    cudaFuncSetAttribute(hgemm<1, 256, 256>,  cudaFuncAttributeMaxDynamicSharedMemorySize, GSMEM);
    cudaFuncSetAttribute(hgemm<2, 256, 1024>, cudaFuncAttributeMaxDynamicSharedMemorySize, GSMEM);
    cudaFuncSetAttribute(hgemm<3, 1024, 256>, cudaFuncAttributeMaxDynamicSharedMemorySize, GSMEM);

    // 0) weight transpose + hi/lo split
    wprep_kernel<<<768, 256>>>(qkv_w,  wqh, wql, 256, 768);
    wprep_kernel<<<256, 256>>>(proj_w, wph, wpl, 256, 256);
    wprep_kernel<<<1024, 256>>>(mlp_w1, w1h, w1l, 256, 1024);
    wprep_kernel<<<1024, 256>>>(mlp_w2, w2h, w2l, 1024, 256);
    // 1) LN1 + roll + window partition -> bf16 hi/lo
    ln_kernel<1><<<ROWS / 8, 256>>>(x, ln1_g, ln1_b, ywh, ywl);
    // 2) QKV GEMM (HMMA, scatter to q/k/v per-head layout, q scaled)
    hgemm<0, 256, 768><<<dim3(12, ROWS / 128), 256, GSMEM>>>(
        ywh, ywl, wqh, wql, qkv_b, nullptr, qb, kb, vb, nullptr, nullptr);
    // 3) windowed attention -> bf16 hi/lo
    attn_kernel<<<4096 * 8, 256>>>(qb, kb, vb, rpb, owh, owl);
    // 4) proj GEMM + window reverse + un-shift + residual -> x2 (fp32)
    hgemm<1, 256, 256><<<dim3(4, ROWS / 128), 256, GSMEM>>>(
        owh, owl, wph, wpl, proj_b, x, x2, nullptr, nullptr, nullptr, nullptr);
    // 5) LN2 -> bf16 hi/lo
    ln_kernel<0><<<ROWS / 8, 256>>>(x2, ln2_g, ln2_b, ywh, ywl);
    // 6) MLP1 + GELU -> bf16 hi/lo hidden
    hgemm<2, 256, 1024><<<dim3(16, ROWS / 128), 256, GSMEM>>>(
        ywh, ywl, w1h, w1l, mlp_b1, nullptr, nullptr, nullptr, nullptr, hh, hl);
    // 7) MLP2 + residual -> out (fp32)
    hgemm<3, 1024, 256><<<dim3(4, ROWS / 128), 256, GSMEM>>>(
        hh, hl, w2h, w2l, mlp_b2, x2, (float*)d_out, nullptr, nullptr, nullptr, nullptr);
    (void)in_sizes; (void)n_in; (void)out_size;
}

// round 13
// speedup vs baseline: 1.8265x; 1.1957x over previous
#include <cuda_runtime.h>
#include <cuda_bf16.h>
#include <math.h>
#include <stdint.h>

// ---------------- problem constants ----------------
#define BSZ   64
#define HH    56
#define WW2   56
#define CCH   256
#define WIN   7
#define NSH   3
#define HEADS 8
#define HD    32
#define NTOK  49
#define ROWS  200704     // BSZ*HH*WW2

typedef unsigned long long u64;
typedef __nv_bfloat16 bf16;

// ---------------- scratch (static device arrays; no allocation) ----------------
__device__ __align__(16) bf16 g_ywh[(size_t)ROWS * CCH];   // LN out hi
__device__ __align__(16) bf16 g_ywl[(size_t)ROWS * CCH];   // LN out lo
__device__ __align__(16) float g_q[(size_t)ROWS * CCH];    // [win*8+head][49][32]
__device__ __align__(16) float g_k[(size_t)ROWS * CCH];
__device__ __align__(16) float g_v[(size_t)ROWS * CCH];
__device__ __align__(16) bf16 g_owh[(size_t)ROWS * CCH];   // attn out hi (window layout)
__device__ __align__(16) bf16 g_owl[(size_t)ROWS * CCH];
__device__ __align__(16) float g_x2[(size_t)ROWS * CCH];   // shortcut + proj (token layout)
__device__ __align__(16) bf16 g_hh[(size_t)ROWS * 1024];   // GELU hidden hi
__device__ __align__(16) bf16 g_hl[(size_t)ROWS * 1024];
// transposed + split weights  [N][K]
__device__ __align__(16) bf16 g_wqh[768 * 256],  g_wql[768 * 256];
__device__ __align__(16) bf16 g_wph[256 * 256],  g_wpl[256 * 256];
__device__ __align__(16) bf16 g_w1h[1024 * 256], g_w1l[1024 * 256];
__device__ __align__(16) bf16 g_w2h[256 * 1024], g_w2l[256 * 1024];

// ---------------- PTX helpers (plain sm_80+ features only) ----------------
__device__ __forceinline__ uint32_t smem_u32(const void* p) {
    uint32_t a;
    asm("{ .reg .u64 t; cvta.to.shared.u64 t, %1; cvt.u32.u64 %0, t; }" : "=r"(a) : "l"(p));
    return a;
}
__device__ __forceinline__ void ldsm4(uint32_t r[4], uint32_t addr) {
    asm volatile("ldmatrix.sync.aligned.m8n8.x4.shared.b16 {%0,%1,%2,%3}, [%4];"
        : "=r"(r[0]), "=r"(r[1]), "=r"(r[2]), "=r"(r[3]) : "r"(addr));
}
__device__ __forceinline__ void mma_bf16(float acc[4], const uint32_t a[4],
                                         uint32_t b0, uint32_t b1) {
    asm volatile("mma.sync.aligned.m16n8k16.row.col.f32.bf16.bf16.f32 "
        "{%0,%1,%2,%3}, {%4,%5,%6,%7}, {%8,%9}, {%0,%1,%2,%3};"
        : "+f"(acc[0]), "+f"(acc[1]), "+f"(acc[2]), "+f"(acc[3])
        : "r"(a[0]), "r"(a[1]), "r"(a[2]), "r"(a[3]), "r"(b0), "r"(b1));
}
#define CP_ASYNC(dst, src) \
    asm volatile("cp.async.cg.shared.global [%0], [%1], 16;" :: "r"(dst), "l"(src))
#define CP_COMMIT() asm volatile("cp.async.commit_group;" ::: "memory")
#define CP_WAIT1()  asm volatile("cp.async.wait_group 1;" ::: "memory")
#define CP_WAIT0()  asm volatile("cp.async.wait_group 0;" ::: "memory")

// ---------------- misc helpers ----------------
__device__ __forceinline__ float gelu_exact(float x) {
    return 0.5f * x * (1.0f + erff(x * 0.7071067811865476f));
}
__device__ __forceinline__ size_t remap_row(int row) {
    int bimg = row / 3136;
    int rem  = row - bimg * 3136;
    int wi   = rem / NTOK;
    int p    = rem - wi * NTOK;
    int whi  = wi >> 3, wwi = wi & 7;
    int ii   = p / 7,   jj  = p - (p / 7) * 7;
    int h = whi * 7 + ii + NSH; if (h >= HH)  h -= HH;
    int w = wwi * 7 + jj + NSH; if (w >= WW2) w -= WW2;
    return (size_t)bimg * 3136 + h * WW2 + w;
}
__device__ __forceinline__ void split_store4(bf16* ph, bf16* pl, size_t off, float4 v) {
    __nv_bfloat162 h0 = __floats2bfloat162_rn(v.x, v.y);
    __nv_bfloat162 h1 = __floats2bfloat162_rn(v.z, v.w);
    float lx = v.x - __bfloat162float(h0.x);
    float ly = v.y - __bfloat162float(h0.y);
    float lz = v.z - __bfloat162float(h1.x);
    float lw = v.w - __bfloat162float(h1.y);
    *(__nv_bfloat162*)(ph + off)     = h0;
    *(__nv_bfloat162*)(ph + off + 2) = h1;
    *(__nv_bfloat162*)(pl + off)     = __floats2bfloat162_rn(lx, ly);
    *(__nv_bfloat162*)(pl + off + 2) = __floats2bfloat162_rn(lz, lw);
}
__device__ __forceinline__ void split_store2(bf16* ph, bf16* pl, size_t off, float2 v) {
    __nv_bfloat162 h = __floats2bfloat162_rn(v.x, v.y);
    float lx = v.x - __bfloat162float(h.x);
    float ly = v.y - __bfloat162float(h.y);
    *(__nv_bfloat162*)(ph + off) = h;
    *(__nv_bfloat162*)(pl + off) = __floats2bfloat162_rn(lx, ly);
}

// ---------------- weight prep: W[K][N] fp32 -> Wt_hi/Wt_lo [N][K] bf16 ----------------
__global__ __launch_bounds__(256)
void wprep_kernel(const float* __restrict__ W, bf16* __restrict__ th,
                  bf16* __restrict__ tl, int K, int N)
{
    int idx = blockIdx.x * 256 + threadIdx.x;
    if (idx >= K * N) return;
    int k = idx / N, n = idx - k * N;
    float w = W[idx];
    bf16 h = __float2bfloat16(w);
    float lo = w - __bfloat162float(h);
    th[(size_t)n * K + k] = h;
    tl[(size_t)n * K + k] = __float2bfloat16(lo);
}

// ---------------- LayerNorm -> bf16 hi/lo.  REMAP=1: rolled gather to window layout ----------------
template<int REMAP>
__global__ __launch_bounds__(256)
void ln_kernel(const float* __restrict__ x, const float* __restrict__ gma,
               const float* __restrict__ bta, bf16* __restrict__ yh,
               bf16* __restrict__ yl)
{
    int orow = blockIdx.x * 8 + (threadIdx.x >> 5);
    int lane = threadIdx.x & 31;
    size_t irow = REMAP ? remap_row(orow) : (size_t)orow;
    const float* xr = x + irow * CCH;
    float4 v0 = *(const float4*)(xr + (lane << 2));
    float4 v1 = *(const float4*)(xr + 128 + (lane << 2));
    float s  = v0.x + v0.y + v0.z + v0.w + v1.x + v1.y + v1.z + v1.w;
    float sq = v0.x*v0.x + v0.y*v0.y + v0.z*v0.z + v0.w*v0.w
             + v1.x*v1.x + v1.y*v1.y + v1.z*v1.z + v1.w*v1.w;
#pragma unroll
    for (int o = 16; o > 0; o >>= 1) {
        s  += __shfl_xor_sync(0xffffffffu, s,  o);
        sq += __shfl_xor_sync(0xffffffffu, sq, o);
    }
    float mu  = s  * 0.00390625f;
    float var = sq * 0.00390625f - mu * mu;
    float inv = rsqrtf(var + 1e-5f);
    float4 g0 = *(const float4*)(gma + (lane << 2));
    float4 g1 = *(const float4*)(gma + 128 + (lane << 2));
    float4 b0 = *(const float4*)(bta + (lane << 2));
    float4 b1 = *(const float4*)(bta + 128 + (lane << 2));
    float4 o0, o1;
    o0.x = (v0.x - mu) * inv * g0.x + b0.x;
    o0.y = (v0.y - mu) * inv * g0.y + b0.y;
    o0.z = (v0.z - mu) * inv * g0.z + b0.z;
    o0.w = (v0.w - mu) * inv * g0.w + b0.w;
    o1.x = (v1.x - mu) * inv * g1.x + b1.x;
    o1.y = (v1.y - mu) * inv * g1.y + b1.y;
    o1.z = (v1.z - mu) * inv * g1.z + b1.z;
    o1.w = (v1.w - mu) * inv * g1.w + b1.w;
    size_t base = (size_t)orow * CCH;
    split_store4(yh, yl, base + (lane << 2), o0);
    split_store4(yh, yl, base + 128 + (lane << 2), o1);
}

// ---------------- HMMA GEMM: block 256x128, warp 64x64, K-chunk 32, hi/lo 3-pass ----------------
// smem stage: A hi 256x80B, A lo, B hi 128x80B, B lo.  3 stages.
#define APITCH 80
#define SA_HI  0
#define SA_LO  20480
#define SB_HI  40960
#define SB_LO  51200
#define STAGE  61440
#define GSMEM  (3 * STAGE)

// EPI: 0 = QKV scatter (+bias, q scale)  1 = proj (+bias, window-reverse, +x residual)
//      2 = MLP1 (+bias, GELU -> bf16 hi/lo)  3 = MLP2 (+bias, +x2 residual)
template<int EPI, int K, int N>
__global__ __launch_bounds__(256, 1)
void hgemm(const bf16* __restrict__ Ah, const bf16* __restrict__ Al,
           const bf16* __restrict__ Bh, const bf16* __restrict__ Bl,
           const float* __restrict__ bias, const float* __restrict__ addsrc,
           float* __restrict__ O0, float* __restrict__ O1, float* __restrict__ O2,
           bf16* __restrict__ P0, bf16* __restrict__ P1)
{
    extern __shared__ char smem[];
    const uint32_t sb = smem_u32(smem);
    const int tid  = threadIdx.x;
    const int wid  = tid >> 5;
    const int lane = tid & 31;
    const int wm   = wid & 3;           // warp m index (0..3), 64 rows each
    const int wn   = wid >> 2;          // warp n index (0..1), 64 cols each
    const int m0   = blockIdx.y << 8;
    const int n0   = blockIdx.x << 7;

    // cp.async load of one 32-K chunk into stage ch%3
    auto LOAD = [&](int ch) {
        const size_t kc0 = (size_t)ch * 32;
        const uint32_t db = sb + (ch % 3) * STAGE;
#pragma unroll
        for (int j = 0; j < 4; j++) {           // A: 1024 granules of 16B per operand
            int g = tid + 256 * j;
            int row = g >> 2, seg = g & 3;
            size_t go = (size_t)(m0 + row) * K + kc0 + seg * 8;
            uint32_t so = row * APITCH + seg * 16;
            CP_ASYNC(db + SA_HI + so, Ah + go);
            CP_ASYNC(db + SA_LO + so, Al + go);
        }
#pragma unroll
        for (int j = 0; j < 2; j++) {           // B: 512 granules per operand
            int g = tid + 256 * j;
            int row = g >> 2, seg = g & 3;
            size_t go = (size_t)(n0 + row) * K + kc0 + seg * 8;
            uint32_t so = row * APITCH + seg * 16;
            CP_ASYNC(db + SB_HI + so, Bh + go);
            CP_ASYNC(db + SB_LO + so, Bl + go);
        }
        CP_COMMIT();
    };

    // ldmatrix per-thread base offsets
    const int q  = lane >> 3, lr = lane & 7;
    const uint32_t aBase = (uint32_t)(wm * 64 + (q & 1) * 8 + lr) * APITCH + (q >> 1) * 16;
    const uint32_t bBase = (uint32_t)(wn * 64 + (q >> 1) * 8 + lr) * APITCH + (q & 1) * 16;

    float acc[4][8][4];                 // [m16 tile][n8 tile][frag]
#pragma unroll
    for (int mt = 0; mt < 4; mt++)
#pragma unroll
        for (int nt = 0; nt < 8; nt++)
#pragma unroll
            for (int r = 0; r < 4; r++) acc[mt][nt][r] = 0.f;

    constexpr int NCH = K / 32;
    LOAD(0);
    LOAD(1);
    for (int i = 0; i < NCH; i++) {
        if (i + 1 < NCH) { CP_WAIT1(); } else { CP_WAIT0(); }
        __syncthreads();
        if (i + 2 < NCH) LOAD(i + 2);
        const uint32_t bb = sb + (i % 3) * STAGE;
#pragma unroll
        for (int ks = 0; ks < 2; ks++) {
            uint32_t ah[4][4], al[4][4], bh[4][4], bl[4][4];
#pragma unroll
            for (int mt = 0; mt < 4; mt++) {
                ldsm4(ah[mt], bb + SA_HI + aBase + mt * (16 * APITCH) + ks * 32);
                ldsm4(al[mt], bb + SA_LO + aBase + mt * (16 * APITCH) + ks * 32);
            }
#pragma unroll
            for (int nt = 0; nt < 4; nt++) {
                ldsm4(bh[nt], bb + SB_HI + bBase + nt * (16 * APITCH) + ks * 32);
                ldsm4(bl[nt], bb + SB_LO + bBase + nt * (16 * APITCH) + ks * 32);
            }
#pragma unroll
            for (int mt = 0; mt < 4; mt++) {
#pragma unroll
                for (int nt = 0; nt < 4; nt++) {
                    mma_bf16(acc[mt][2 * nt],     ah[mt], bh[nt][0], bh[nt][1]);
                    mma_bf16(acc[mt][2 * nt],     ah[mt], bl[nt][0], bl[nt][1]);
                    mma_bf16(acc[mt][2 * nt],     al[mt], bh[nt][0], bh[nt][1]);
                    mma_bf16(acc[mt][2 * nt + 1], ah[mt], bh[nt][2], bh[nt][3]);
                    mma_bf16(acc[mt][2 * nt + 1], ah[mt], bl[nt][2], bl[nt][3]);
                    mma_bf16(acc[mt][2 * nt + 1], al[mt], bh[nt][2], bh[nt][3]);
                }
            }
        }
    }

    // ---- epilogue: direct register -> gmem (float2 granularity) ----
    const int gid = lane >> 2, tig = lane & 3;
    const float sc = 0.17677669529663687f;   // 1/sqrt(32)
#pragma unroll
    for (int mt = 0; mt < 4; mt++) {
#pragma unroll
        for (int half = 0; half < 2; half++) {
            const int row = m0 + wm * 64 + mt * 16 + gid + half * 8;
            // per-row precompute
            int win = 0, nn = 0;
            size_t dr = 0;
            if (EPI == 0) { win = row / NTOK; nn = row - win * NTOK; }
            if (EPI == 1) { dr = remap_row(row); }
#pragma unroll
            for (int nt = 0; nt < 8; nt++) {
                const int col = n0 + wn * 64 + (nt >> 1) * 16 + (nt & 1) * 8 + tig * 2;
                float2 v = make_float2(acc[mt][nt][half * 2], acc[mt][nt][half * 2 + 1]);
                float2 b2 = *(const float2*)(bias + col);
                v.x += b2.x; v.y += b2.y;
                if (EPI == 0) {
                    const int part = col >> 8;
                    const int head = (col >> 5) & 7;
                    const int d0   = col & 31;
                    if (part == 0) { v.x *= sc; v.y *= sc; }
                    float* dst = (part == 0) ? O0 : ((part == 1) ? O1 : O2);
                    *(float2*)&dst[((size_t)((win << 3) + head) * NTOK + nn) * 32 + d0] = v;
                } else if (EPI == 1) {
                    float2 x2v = *(const float2*)(addsrc + dr * CCH + col);
                    v.x += x2v.x; v.y += x2v.y;
                    *(float2*)(O0 + dr * CCH + col) = v;
                } else if (EPI == 2) {
                    v.x = gelu_exact(v.x); v.y = gelu_exact(v.y);
                    split_store2(P0, P1, (size_t)row * N + col, v);
                } else {
                    float2 x2v = *(const float2*)(addsrc + (size_t)row * CCH + col);
                    v.x += x2v.x; v.y += x2v.y;
                    *(float2*)(O0 + (size_t)row * CCH + col) = v;
                }
            }
        }
    }
}

// ---------------- attention: one block per (window, head); outputs bf16 hi/lo ----------------
__global__ __launch_bounds__(256)
void attn_kernel(const float* __restrict__ q, const float* __restrict__ k,
                 const float* __restrict__ v, const float* __restrict__ rpb,
                 bf16* __restrict__ oh, bf16* __restrict__ ol)
{
    __shared__ float qt[32][52];
    __shared__ float kt[32][52];
    __shared__ float vs[49][32];
    __shared__ float S[52][52];
    const int wh   = blockIdx.x;
    const int win  = wh >> 3;
    const int head = wh & 7;
    const int wimg = win & 63;
    const int whi  = wimg >> 3, wwi = wimg & 7;
    const int t    = threadIdx.x;
    const size_t base = (size_t)wh * (NTOK * HD);

    for (int idx = t; idx < NTOK * HD; idx += 256) {
        int n = idx >> 5, d = idx & 31;
        qt[d][n] = q[base + idx];
        kt[d][n] = k[base + idx];
        vs[n][d] = v[base + idx];
    }
    if (t < 32) {
        qt[t][49] = 0.f; qt[t][50] = 0.f; qt[t][51] = 0.f;
        kt[t][49] = 0.f; kt[t][50] = 0.f; kt[t][51] = 0.f;
    }
    __syncthreads();

    if (t < 169) {
        const int ti = t / 13, tj = t - (t / 13) * 13;
        const int i0 = ti << 2, j0 = tj << 2;
        float acc[4][4];
#pragma unroll
        for (int r = 0; r < 4; r++)
#pragma unroll
            for (int c = 0; c < 4; c++) acc[r][c] = 0.f;
#pragma unroll 8
        for (int d = 0; d < 32; d++) {
            float4 qa = *(const float4*)&qt[d][i0];
            float4 kb = *(const float4*)&kt[d][j0];
            float av[4] = {qa.x, qa.y, qa.z, qa.w};
            float bv[4] = {kb.x, kb.y, kb.z, kb.w};
#pragma unroll
            for (int r = 0; r < 4; r++)
#pragma unroll
                for (int c = 0; c < 4; c++)
                    acc[r][c] = fmaf(av[r], bv[c], acc[r][c]);
        }
#pragma unroll
        for (int r = 0; r < 4; r++) {
            int i = i0 + r;
            if (i < NTOK) {
                int ri = i / 7, ci = i - ri * 7;
                int hhp = whi * 7 + ri;
                int wwp = wwi * 7 + ci;
                int regi = ((hhp < 49) ? 0 : ((hhp < 53) ? 1 : 2)) * 3
                         + ((wwp < 49) ? 0 : ((wwp < 53) ? 1 : 2));
#pragma unroll
                for (int c = 0; c < 4; c++) {
                    int j = j0 + c;
                    float val;
                    if (j < NTOK) {
                        int rj = j / 7, cj = j - rj * 7;
                        float bias = rpb[((ri - rj + 6) * 13 + (ci - cj + 6)) * HEADS + head];
                        int hhq = whi * 7 + rj;
                        int wwq = wwi * 7 + cj;
                        int regj = ((hhq < 49) ? 0 : ((hhq < 53) ? 1 : 2)) * 3
                                 + ((wwq < 49) ? 0 : ((wwq < 53) ? 1 : 2));
                        val = acc[r][c] + bias + ((regi == regj) ? 0.f : -100.f);
                    } else {
                        val = -1e30f;
                    }
                    S[i][j] = val;
                }
            }
        }
    }
    __syncthreads();

    if (t < NTOK) {
        float mx = -1e30f;
#pragma unroll
        for (int j = 0; j < NTOK; j++) mx = fmaxf(mx, S[t][j]);
        float s = 0.f;
#pragma unroll
        for (int j = 0; j < NTOK; j++) {
            float e = __expf(S[t][j] - mx);
            S[t][j] = e; s += e;
        }
        float inv = 1.f / s;
#pragma unroll
        for (int j = 0; j < NTOK; j++) S[t][j] *= inv;
    }
    __syncthreads();

    if (t < 104) {
        const int ti = t >> 3, td = t & 7;
        const int i0 = ti << 2, d0 = td << 2;
        float acc[4][4];
#pragma unroll
        for (int r = 0; r < 4; r++)
#pragma unroll
            for (int c = 0; c < 4; c++) acc[r][c] = 0.f;
#pragma unroll 7
        for (int j = 0; j < NTOK; j++) {
            float4 v4 = *(const float4*)&vs[j][d0];
#pragma unroll
            for (int r = 0; r < 4; r++) {
                float p = S[i0 + r][j];
                acc[r][0] = fmaf(p, v4.x, acc[r][0]);
                acc[r][1] = fmaf(p, v4.y, acc[r][1]);
                acc[r][2] = fmaf(p, v4.z, acc[r][2]);
                acc[r][3] = fmaf(p, v4.w, acc[r][3]);
            }
        }
#pragma unroll
        for (int r = 0; r < 4; r++) {
            int i = i0 + r;
            if (i < NTOK) {
                float4 rr = make_float4(acc[r][0], acc[r][1], acc[r][2], acc[r][3]);
                split_store4(oh, ol,
                             ((size_t)(win * NTOK + i)) * CCH + head * HD + d0, rr);
            }
        }
    }
}

// ---------------- launch ----------------
extern "C" void kernel_launch(void* const* d_in, const int* in_sizes, int n_in,
                              void* d_out, int out_size)
{
    const float* x      = (const float*)d_in[0];
    const float* ln1_g  = (const float*)d_in[1];
    const float* ln1_b  = (const float*)d_in[2];
    const float* qkv_w  = (const float*)d_in[3];
    const float* qkv_b  = (const float*)d_in[4];
    const float* rpb    = (const float*)d_in[5];
    const float* proj_w = (const float*)d_in[6];
    const float* proj_b = (const float*)d_in[7];
    const float* ln2_g  = (const float*)d_in[8];
    const float* ln2_b  = (const float*)d_in[9];
    const float* mlp_w1 = (const float*)d_in[10];
    const float* mlp_b1 = (const float*)d_in[11];
    const float* mlp_w2 = (const float*)d_in[12];
    const float* mlp_b2 = (const float*)d_in[13];

    bf16 *ywh, *ywl, *owh, *owl, *hh, *hl;
    bf16 *wqh, *wql, *wph, *wpl, *w1h, *w1l, *w2h, *w2l;
    float *qb, *kb, *vb, *x2;
    cudaGetSymbolAddress((void**)&ywh, g_ywh);
    cudaGetSymbolAddress((void**)&ywl, g_ywl);
    cudaGetSymbolAddress((void**)&qb,  g_q);
    cudaGetSymbolAddress((void**)&kb,  g_k);
    cudaGetSymbolAddress((void**)&vb,  g_v);
    cudaGetSymbolAddress((void**)&owh, g_owh);
    cudaGetSymbolAddress((void**)&owl, g_owl);
    cudaGetSymbolAddress((void**)&x2,  g_x2);
    cudaGetSymbolAddress((void**)&hh,  g_hh);
    cudaGetSymbolAddress((void**)&hl,  g_hl);
    cudaGetSymbolAddress((void**)&wqh, g_wqh);
    cudaGetSymbolAddress((void**)&wql, g_wql);
    cudaGetSymbolAddress((void**)&wph, g_wph);
    cudaGetSymbolAddress((void**)&wpl, g_wpl);
    cudaGetSymbolAddress((void**)&w1h, g_w1h);
    cudaGetSymbolAddress((void**)&w1l, g_w1l);
    cudaGetSymbolAddress((void**)&w2h, g_w2h);
    cudaGetSymbolAddress((void**)&w2l, g_w2l);

    cudaFuncSetAttribute(hgemm<0, 256, 768>,  cudaFuncAttributeMaxDynamicSharedMemorySize, GSMEM);
    cudaFuncSetAttribute(hgemm<1, 256, 256>,  cudaFuncAttributeMaxDynamicSharedMemorySize, GSMEM);
    cudaFuncSetAttribute(hgemm<2, 256, 1024>, cudaFuncAttributeMaxDynamicSharedMemorySize, GSMEM);
    cudaFuncSetAttribute(hgemm<3, 1024, 256>, cudaFuncAttributeMaxDynamicSharedMemorySize, GSMEM);

    // 0) weight transpose + hi/lo split
    wprep_kernel<<<768, 256>>>(qkv_w,  wqh, wql, 256, 768);
    wprep_kernel<<<256, 256>>>(proj_w, wph, wpl, 256, 256);
    wprep_kernel<<<1024, 256>>>(mlp_w1, w1h, w1l, 256, 1024);
    wprep_kernel<<<1024, 256>>>(mlp_w2, w2h, w2l, 1024, 256);
    // 1) LN1 + roll + window partition -> bf16 hi/lo
    ln_kernel<1><<<ROWS / 8, 256>>>(x, ln1_g, ln1_b, ywh, ywl);
    // 2) QKV GEMM (HMMA 256x128 tiles, scatter to q/k/v per-head layout, q scaled)
    hgemm<0, 256, 768><<<dim3(6, ROWS / 256), 256, GSMEM>>>(
        ywh, ywl, wqh, wql, qkv_b, nullptr, qb, kb, vb, nullptr, nullptr);
    // 3) windowed attention -> bf16 hi/lo
    attn_kernel<<<4096 * 8, 256>>>(qb, kb, vb, rpb, owh, owl);
    // 4) proj GEMM + window reverse + un-shift + residual -> x2 (fp32)
    hgemm<1, 256, 256><<<dim3(2, ROWS / 256), 256, GSMEM>>>(
        owh, owl, wph, wpl, proj_b, x, x2, nullptr, nullptr, nullptr, nullptr);
    // 5) LN2 -> bf16 hi/lo
    ln_kernel<0><<<ROWS / 8, 256>>>(x2, ln2_g, ln2_b, ywh, ywl);
    // 6) MLP1 + GELU -> bf16 hi/lo hidden
    hgemm<2, 256, 1024><<<dim3(8, ROWS / 256), 256, GSMEM>>>(
        ywh, ywl, w1h, w1l, mlp_b1, nullptr, nullptr, nullptr, nullptr, hh, hl);
    // 7) MLP2 + residual -> out (fp32)
    hgemm<3, 1024, 256><<<dim3(2, ROWS / 256), 256, GSMEM>>>(
        hh, hl, w2h, w2l, mlp_b2, x2, (float*)d_out, nullptr, nullptr, nullptr, nullptr);
    (void)in_sizes; (void)n_in; (void)out_size;
}

// round 15
// speedup vs baseline: 1.8271x; 1.0003x over previous
#include <cuda_runtime.h>
#include <cuda_bf16.h>
#include <math.h>
#include <stdint.h>

// ---------------- problem constants ----------------
#define BSZ   64
#define HH    56
#define WW2   56
#define CCH   256
#define WIN   7
#define NSH   3
#define HEADS 8
#define HD    32
#define NTOK  49
#define ROWS  200704     // BSZ*HH*WW2

typedef unsigned long long u64;
typedef __nv_bfloat16 bf16;

// ---------------- scratch (static device arrays; no allocation) ----------------
__device__ __align__(16) bf16 g_ywh[(size_t)ROWS * CCH];   // LN out hi
__device__ __align__(16) bf16 g_ywl[(size_t)ROWS * CCH];   // LN out lo
__device__ __align__(16) float g_q[(size_t)ROWS * CCH];    // [win*8+head][49][32]
__device__ __align__(16) float g_k[(size_t)ROWS * CCH];
__device__ __align__(16) float g_v[(size_t)ROWS * CCH];
__device__ __align__(16) bf16 g_owh[(size_t)ROWS * CCH];   // attn out hi (window layout)
__device__ __align__(16) bf16 g_owl[(size_t)ROWS * CCH];
__device__ __align__(16) float g_x2[(size_t)ROWS * CCH];   // shortcut + proj (token layout)
__device__ __align__(16) bf16 g_hh[(size_t)ROWS * 1024];   // GELU hidden hi
__device__ __align__(16) bf16 g_hl[(size_t)ROWS * 1024];
// transposed + split weights  [N][K]
__device__ __align__(16) bf16 g_wqh[768 * 256],  g_wql[768 * 256];
__device__ __align__(16) bf16 g_wph[256 * 256],  g_wpl[256 * 256];
__device__ __align__(16) bf16 g_w1h[1024 * 256], g_w1l[1024 * 256];
__device__ __align__(16) bf16 g_w2h[256 * 1024], g_w2l[256 * 1024];

// ---------------- PTX helpers (plain sm_80+ features only) ----------------
__device__ __forceinline__ uint32_t smem_u32(const void* p) {
    uint32_t a;
    asm("{ .reg .u64 t; cvta.to.shared.u64 t, %1; cvt.u32.u64 %0, t; }" : "=r"(a) : "l"(p));
    return a;
}
__device__ __forceinline__ void ldsm4(uint32_t r[4], uint32_t addr) {
    asm volatile("ldmatrix.sync.aligned.m8n8.x4.shared.b16 {%0,%1,%2,%3}, [%4];"
        : "=r"(r[0]), "=r"(r[1]), "=r"(r[2]), "=r"(r[3]) : "r"(addr));
}
__device__ __forceinline__ void mma_bf16(float acc[4], const uint32_t a[4],
                                         uint32_t b0, uint32_t b1) {
    asm volatile("mma.sync.aligned.m16n8k16.row.col.f32.bf16.bf16.f32 "
        "{%0,%1,%2,%3}, {%4,%5,%6,%7}, {%8,%9}, {%0,%1,%2,%3};"
        : "+f"(acc[0]), "+f"(acc[1]), "+f"(acc[2]), "+f"(acc[3])
        : "r"(a[0]), "r"(a[1]), "r"(a[2]), "r"(a[3]), "r"(b0), "r"(b1));
}
#define CP_ASYNC(dst, src) \
    asm volatile("cp.async.cg.shared.global [%0], [%1], 16;" :: "r"(dst), "l"(src))
#define CP_COMMIT() asm volatile("cp.async.commit_group;" ::: "memory")
#define CP_WAIT1()  asm volatile("cp.async.wait_group 1;" ::: "memory")
#define CP_WAIT0()  asm volatile("cp.async.wait_group 0;" ::: "memory")

// ---------------- misc helpers ----------------
__device__ __forceinline__ float gelu_exact(float x) {
    return 0.5f * x * (1.0f + erff(x * 0.7071067811865476f));
}
__device__ __forceinline__ size_t remap_row(int row) {
    int bimg = row / 3136;
    int rem  = row - bimg * 3136;
    int wi   = rem / NTOK;
    int p    = rem - wi * NTOK;
    int whi  = wi >> 3, wwi = wi & 7;
    int ii   = p / 7,   jj  = p - (p / 7) * 7;
    int h = whi * 7 + ii + NSH; if (h >= HH)  h -= HH;
    int w = wwi * 7 + jj + NSH; if (w >= WW2) w -= WW2;
    return (size_t)bimg * 3136 + h * WW2 + w;
}
__device__ __forceinline__ void split_store4(bf16* ph, bf16* pl, size_t off, float4 v) {
    __nv_bfloat162 h0 = __floats2bfloat162_rn(v.x, v.y);
    __nv_bfloat162 h1 = __floats2bfloat162_rn(v.z, v.w);
    float lx = v.x - __bfloat162float(h0.x);
    float ly = v.y - __bfloat162float(h0.y);
    float lz = v.z - __bfloat162float(h1.x);
    float lw = v.w - __bfloat162float(h1.y);
    *(__nv_bfloat162*)(ph + off)     = h0;
    *(__nv_bfloat162*)(ph + off + 2) = h1;
    *(__nv_bfloat162*)(pl + off)     = __floats2bfloat162_rn(lx, ly);
    *(__nv_bfloat162*)(pl + off + 2) = __floats2bfloat162_rn(lz, lw);
}
__device__ __forceinline__ void split_store2(bf16* ph, bf16* pl, size_t off, float2 v) {
    __nv_bfloat162 h = __floats2bfloat162_rn(v.x, v.y);
    float lx = v.x - __bfloat162float(h.x);
    float ly = v.y - __bfloat162float(h.y);
    *(__nv_bfloat162*)(ph + off) = h;
    *(__nv_bfloat162*)(pl + off) = __floats2bfloat162_rn(lx, ly);
}

// ---------------- weight prep: W[K][N] fp32 -> Wt_hi/Wt_lo [N][K] bf16 ----------------
__global__ __launch_bounds__(256)
void wprep_kernel(const float* __restrict__ W, bf16* __restrict__ th,
                  bf16* __restrict__ tl, int K, int N)
{
    int idx = blockIdx.x * 256 + threadIdx.x;
    if (idx >= K * N) return;
    int k = idx / N, n = idx - k * N;
    float w = W[idx];
    bf16 h = __float2bfloat16(w);
    float lo = w - __bfloat162float(h);
    th[(size_t)n * K + k] = h;
    tl[(size_t)n * K + k] = __float2bfloat16(lo);
}

// ---------------- LayerNorm -> bf16 hi/lo.  REMAP=1: rolled gather to window layout ----------------
template<int REMAP>
__global__ __launch_bounds__(256)
void ln_kernel(const float* __restrict__ x, const float* __restrict__ gma,
               const float* __restrict__ bta, bf16* __restrict__ yh,
               bf16* __restrict__ yl)
{
    int orow = blockIdx.x * 8 + (threadIdx.x >> 5);
    int lane = threadIdx.x & 31;
    size_t irow = REMAP ? remap_row(orow) : (size_t)orow;
    const float* xr = x + irow * CCH;
    float4 v0 = *(const float4*)(xr + (lane << 2));
    float4 v1 = *(const float4*)(xr + 128 + (lane << 2));
    float s  = v0.x + v0.y + v0.z + v0.w + v1.x + v1.y + v1.z + v1.w;
    float sq = v0.x*v0.x + v0.y*v0.y + v0.z*v0.z + v0.w*v0.w
             + v1.x*v1.x + v1.y*v1.y + v1.z*v1.z + v1.w*v1.w;
#pragma unroll
    for (int o = 16; o > 0; o >>= 1) {
        s  += __shfl_xor_sync(0xffffffffu, s,  o);
        sq += __shfl_xor_sync(0xffffffffu, sq, o);
    }
    float mu  = s  * 0.00390625f;
    float var = sq * 0.00390625f - mu * mu;
    float inv = rsqrtf(var + 1e-5f);
    float4 g0 = *(const float4*)(gma + (lane << 2));
    float4 g1 = *(const float4*)(gma + 128 + (lane << 2));
    float4 b0 = *(const float4*)(bta + (lane << 2));
    float4 b1 = *(const float4*)(bta + 128 + (lane << 2));
    float4 o0, o1;
    o0.x = (v0.x - mu) * inv * g0.x + b0.x;
    o0.y = (v0.y - mu) * inv * g0.y + b0.y;
    o0.z = (v0.z - mu) * inv * g0.z + b0.z;
    o0.w = (v0.w - mu) * inv * g0.w + b0.w;
    o1.x = (v1.x - mu) * inv * g1.x + b1.x;
    o1.y = (v1.y - mu) * inv * g1.y + b1.y;
    o1.z = (v1.z - mu) * inv * g1.z + b1.z;
    o1.w = (v1.w - mu) * inv * g1.w + b1.w;
    size_t base = (size_t)orow * CCH;
    split_store4(yh, yl, base + (lane << 2), o0);
    split_store4(yh, yl, base + 128 + (lane << 2), o1);
}

// ---------------- HMMA GEMM: block 256x128, warp 64x64, K-chunk 32, hi/lo 3-pass ----------------
// smem stage: A hi 256x80B, A lo, B hi 128x80B, B lo.  3 stages.
#define APITCH 80
#define SA_HI  0
#define SA_LO  20480
#define SB_HI  40960
#define SB_LO  51200
#define STAGE  61440
#define GSMEM  (3 * STAGE)

// EPI: 0 = QKV scatter (+bias, q scale)  1 = proj (+bias, window-reverse, +x residual)
//      2 = MLP1 (+bias, GELU -> bf16 hi/lo)  3 = MLP2 (+bias, +x2 residual)
template<int EPI, int K, int N>
__global__ __launch_bounds__(256, 1)
void hgemm(const bf16* __restrict__ Ah, const bf16* __restrict__ Al,
           const bf16* __restrict__ Bh, const bf16* __restrict__ Bl,
           const float* __restrict__ bias, const float* __restrict__ addsrc,
           float* __restrict__ O0, float* __restrict__ O1, float* __restrict__ O2,
           bf16* __restrict__ P0, bf16* __restrict__ P1)
{
    extern __shared__ char smem[];
    const uint32_t sb = smem_u32(smem);
    const int tid  = threadIdx.x;
    const int wid  = tid >> 5;
    const int lane = tid & 31;
    const int wm   = wid & 3;           // warp m index (0..3), 64 rows each
    const int wn   = wid >> 2;          // warp n index (0..1), 64 cols each
    const int m0   = blockIdx.y << 8;
    const int n0   = blockIdx.x << 7;

    // cp.async load of one 32-K chunk into stage ch%3
    auto LOAD = [&](int ch) {
        const size_t kc0 = (size_t)ch * 32;
        const uint32_t db = sb + (ch % 3) * STAGE;
#pragma unroll
        for (int j = 0; j < 4; j++) {           // A: 1024 granules of 16B per operand
            int g = tid + 256 * j;
            int row = g >> 2, seg = g & 3;
            size_t go = (size_t)(m0 + row) * K + kc0 + seg * 8;
            uint32_t so = row * APITCH + seg * 16;
            CP_ASYNC(db + SA_HI + so, Ah + go);
            CP_ASYNC(db + SA_LO + so, Al + go);
        }
#pragma unroll
        for (int j = 0; j < 2; j++) {           // B: 512 granules per operand
            int g = tid + 256 * j;
            int row = g >> 2, seg = g & 3;
            size_t go = (size_t)(n0 + row) * K + kc0 + seg * 8;
            uint32_t so = row * APITCH + seg * 16;
            CP_ASYNC(db + SB_HI + so, Bh + go);
            CP_ASYNC(db + SB_LO + so, Bl + go);
        }
        CP_COMMIT();
    };

    // ldmatrix per-thread base offsets
    const int q  = lane >> 3, lr = lane & 7;
    const uint32_t aBase = (uint32_t)(wm * 64 + (q & 1) * 8 + lr) * APITCH + (q >> 1) * 16;
    const uint32_t bBase = (uint32_t)(wn * 64 + (q >> 1) * 8 + lr) * APITCH + (q & 1) * 16;

    float acc[4][8][4];                 // [m16 tile][n8 tile][frag]
#pragma unroll
    for (int mt = 0; mt < 4; mt++)
#pragma unroll
        for (int nt = 0; nt < 8; nt++)
#pragma unroll
            for (int r = 0; r < 4; r++) acc[mt][nt][r] = 0.f;

    constexpr int NCH = K / 32;
    LOAD(0);
    LOAD(1);
    for (int i = 0; i < NCH; i++) {
        if (i + 1 < NCH) { CP_WAIT1(); } else { CP_WAIT0(); }
        __syncthreads();
        if (i + 2 < NCH) LOAD(i + 2);
        const uint32_t bb = sb + (i % 3) * STAGE;
#pragma unroll
        for (int ks = 0; ks < 2; ks++) {
            uint32_t ah[4][4], al[4][4], bh[4][4], bl[4][4];
#pragma unroll
            for (int mt = 0; mt < 4; mt++) {
                ldsm4(ah[mt], bb + SA_HI + aBase + mt * (16 * APITCH) + ks * 32);
                ldsm4(al[mt], bb + SA_LO + aBase + mt * (16 * APITCH) + ks * 32);
            }
#pragma unroll
            for (int nt = 0; nt < 4; nt++) {
                ldsm4(bh[nt], bb + SB_HI + bBase + nt * (16 * APITCH) + ks * 32);
                ldsm4(bl[nt], bb + SB_LO + bBase + nt * (16 * APITCH) + ks * 32);
            }
            // pass-major order: 32 independent MMAs between reuses of any
            // accumulator (same per-accumulator addition order as before:
            // hh, then hl, then lh -> bit-identical result).
#pragma unroll
            for (int mt = 0; mt < 4; mt++)
#pragma unroll
                for (int nt = 0; nt < 4; nt++) {
                    mma_bf16(acc[mt][2 * nt],     ah[mt], bh[nt][0], bh[nt][1]);
                    mma_bf16(acc[mt][2 * nt + 1], ah[mt], bh[nt][2], bh[nt][3]);
                }
#pragma unroll
            for (int mt = 0; mt < 4; mt++)
#pragma unroll
                for (int nt = 0; nt < 4; nt++) {
                    mma_bf16(acc[mt][2 * nt],     ah[mt], bl[nt][0], bl[nt][1]);
                    mma_bf16(acc[mt][2 * nt + 1], ah[mt], bl[nt][2], bl[nt][3]);
                }
#pragma unroll
            for (int mt = 0; mt < 4; mt++)
#pragma unroll
                for (int nt = 0; nt < 4; nt++) {
                    mma_bf16(acc[mt][2 * nt],     al[mt], bh[nt][0], bh[nt][1]);
                    mma_bf16(acc[mt][2 * nt + 1], al[mt], bh[nt][2], bh[nt][3]);
                }
        }
    }

    // ---- epilogue: direct register -> gmem (float2 granularity) ----
    const int gid = lane >> 2, tig = lane & 3;
    const float sc = 0.17677669529663687f;   // 1/sqrt(32)
#pragma unroll
    for (int mt = 0; mt < 4; mt++) {
#pragma unroll
        for (int half = 0; half < 2; half++) {
            const int row = m0 + wm * 64 + mt * 16 + gid + half * 8;
            // per-row precompute
            int win = 0, nn = 0;
            size_t dr = 0;
            if (EPI == 0) { win = row / NTOK; nn = row - win * NTOK; }
            if (EPI == 1) { dr = remap_row(row); }
#pragma unroll
            for (int nt = 0; nt < 8; nt++) {
                const int col = n0 + wn * 64 + (nt >> 1) * 16 + (nt & 1) * 8 + tig * 2;
                float2 v = make_float2(acc[mt][nt][half * 2], acc[mt][nt][half * 2 + 1]);
                float2 b2 = *(const float2*)(bias + col);
                v.x += b2.x; v.y += b2.y;
                if (EPI == 0) {
                    const int part = col >> 8;
                    const int head = (col >> 5) & 7;
                    const int d0   = col & 31;
                    if (part == 0) { v.x *= sc; v.y *= sc; }
                    float* dst = (part == 0) ? O0 : ((part == 1) ? O1 : O2);
                    *(float2*)&dst[((size_t)((win << 3) + head) * NTOK + nn) * 32 + d0] = v;
                } else if (EPI == 1) {
                    float2 x2v = *(const float2*)(addsrc + dr * CCH + col);
                    v.x += x2v.x; v.y += x2v.y;
                    *(float2*)(O0 + dr * CCH + col) = v;
                } else if (EPI == 2) {
                    v.x = gelu_exact(v.x); v.y = gelu_exact(v.y);
                    split_store2(P0, P1, (size_t)row * N + col, v);
                } else {
                    float2 x2v = *(const float2*)(addsrc + (size_t)row * CCH + col);
                    v.x += x2v.x; v.y += x2v.y;
                    *(float2*)(O0 + (size_t)row * CCH + col) = v;
                }
            }
        }
    }
}

// ---------------- attention: one block per (window, head); outputs bf16 hi/lo ----------------
__global__ __launch_bounds__(256)
void attn_kernel(const float* __restrict__ q, const float* __restrict__ k,
                 const float* __restrict__ v, const float* __restrict__ rpb,
                 bf16* __restrict__ oh, bf16* __restrict__ ol)
{
    __shared__ float qt[32][52];
    __shared__ float kt[32][52];
    __shared__ float vs[49][32];
    __shared__ float S[52][52];
    const int wh   = blockIdx.x;
    const int win  = wh >> 3;
    const int head = wh & 7;
    const int wimg = win & 63;
    const int whi  = wimg >> 3, wwi = wimg & 7;
    const int t    = threadIdx.x;
    const size_t base = (size_t)wh * (NTOK * HD);

    for (int idx = t; idx < NTOK * HD; idx += 256) {
        int n = idx >> 5, d = idx & 31;
        qt[d][n] = q[base + idx];
        kt[d][n] = k[base + idx];
        vs[n][d] = v[base + idx];
    }
    if (t < 32) {
        qt[t][49] = 0.f; qt[t][50] = 0.f; qt[t][51] = 0.f;
        kt[t][49] = 0.f; kt[t][50] = 0.f; kt[t][51] = 0.f;
    }
    __syncthreads();

    if (t < 169) {
        const int ti = t / 13, tj = t - (t / 13) * 13;
        const int i0 = ti << 2, j0 = tj << 2;
        float acc[4][4];
#pragma unroll
        for (int r = 0; r < 4; r++)
#pragma unroll
            for (int c = 0; c < 4; c++) acc[r][c] = 0.f;
#pragma unroll 8
        for (int d = 0; d < 32; d++) {
            float4 qa = *(const float4*)&qt[d][i0];
            float4 kb = *(const float4*)&kt[d][j0];
            float av[4] = {qa.x, qa.y, qa.z, qa.w};
            float bv[4] = {kb.x, kb.y, kb.z, kb.w};
#pragma unroll
            for (int r = 0; r < 4; r++)
#pragma unroll
                for (int c = 0; c < 4; c++)
                    acc[r][c] = fmaf(av[r], bv[c], acc[r][c]);
        }
#pragma unroll
        for (int r = 0; r < 4; r++) {
            int i = i0 + r;
            if (i < NTOK) {
                int ri = i / 7, ci = i - ri * 7;
                int hhp = whi * 7 + ri;
                int wwp = wwi * 7 + ci;
                int regi = ((hhp < 49) ? 0 : ((hhp < 53) ? 1 : 2)) * 3
                         + ((wwp < 49) ? 0 : ((wwp < 53) ? 1 : 2));
#pragma unroll
                for (int c = 0; c < 4; c++) {
                    int j = j0 + c;
                    float val;
                    if (j < NTOK) {
                        int rj = j / 7, cj = j - rj * 7;
                        float bias = rpb[((ri - rj + 6) * 13 + (ci - cj + 6)) * HEADS + head];
                        int hhq = whi * 7 + rj;
                        int wwq = wwi * 7 + cj;
                        int regj = ((hhq < 49) ? 0 : ((hhq < 53) ? 1 : 2)) * 3
                                 + ((wwq < 49) ? 0 : ((wwq < 53) ? 1 : 2));
                        val = acc[r][c] + bias + ((regi == regj) ? 0.f : -100.f);
                    } else {
                        val = -1e30f;
                    }
                    S[i][j] = val;
                }
            }
        }
    }
    __syncthreads();

    if (t < NTOK) {
        float mx = -1e30f;
#pragma unroll
        for (int j = 0; j < NTOK; j++) mx = fmaxf(mx, S[t][j]);
        float s = 0.f;
#pragma unroll
        for (int j = 0; j < NTOK; j++) {
            float e = __expf(S[t][j] - mx);
            S[t][j] = e; s += e;
        }
        float inv = 1.f / s;
#pragma unroll
        for (int j = 0; j < NTOK; j++) S[t][j] *= inv;
    }
    __syncthreads();

    if (t < 104) {
        const int ti = t >> 3, td = t & 7;
        const int i0 = ti << 2, d0 = td << 2;
        float acc[4][4];
#pragma unroll
        for (int r = 0; r < 4; r++)
#pragma unroll
            for (int c = 0; c < 4; c++) acc[r][c] = 0.f;
#pragma unroll 7
        for (int j = 0; j < NTOK; j++) {
            float4 v4 = *(const float4*)&vs[j][d0];
#pragma unroll
            for (int r = 0; r < 4; r++) {
                float p = S[i0 + r][j];
                acc[r][0] = fmaf(p, v4.x, acc[r][0]);
                acc[r][1] = fmaf(p, v4.y, acc[r][1]);
                acc[r][2] = fmaf(p, v4.z, acc[r][2]);
                acc[r][3] = fmaf(p, v4.w, acc[r][3]);
            }
        }
#pragma unroll
        for (int r = 0; r < 4; r++) {
            int i = i0 + r;
            if (i < NTOK) {
                float4 rr = make_float4(acc[r][0], acc[r][1], acc[r][2], acc[r][3]);
                split_store4(oh, ol,
                             ((size_t)(win * NTOK + i)) * CCH + head * HD + d0, rr);
            }
        }
    }
}

// ---------------- launch ----------------
extern "C" void kernel_launch(void* const* d_in, const int* in_sizes, int n_in,
                              void* d_out, int out_size)
{
    const float* x      = (const float*)d_in[0];
    const float* ln1_g  = (const float*)d_in[1];
    const float* ln1_b  = (const float*)d_in[2];
    const float* qkv_w  = (const float*)d_in[3];
    const float* qkv_b  = (const float*)d_in[4];
    const float* rpb    = (const float*)d_in[5];
    const float* proj_w = (const float*)d_in[6];
    const float* proj_b = (const float*)d_in[7];
    const float* ln2_g  = (const float*)d_in[8];
    const float* ln2_b  = (const float*)d_in[9];
    const float* mlp_w1 = (const float*)d_in[10];
    const float* mlp_b1 = (const float*)d_in[11];
    const float* mlp_w2 = (const float*)d_in[12];
    const float* mlp_b2 = (const float*)d_in[13];

    bf16 *ywh, *ywl, *owh, *owl, *hh, *hl;
    bf16 *wqh, *wql, *wph, *wpl, *w1h, *w1l, *w2h, *w2l;
    float *qb, *kb, *vb, *x2;
    cudaGetSymbolAddress((void**)&ywh, g_ywh);
    cudaGetSymbolAddress((void**)&ywl, g_ywl);
    cudaGetSymbolAddress((void**)&qb,  g_q);
    cudaGetSymbolAddress((void**)&kb,  g_k);
    cudaGetSymbolAddress((void**)&vb,  g_v);
    cudaGetSymbolAddress((void**)&owh, g_owh);
    cudaGetSymbolAddress((void**)&owl, g_owl);
    cudaGetSymbolAddress((void**)&x2,  g_x2);
    cudaGetSymbolAddress((void**)&hh,  g_hh);
    cudaGetSymbolAddress((void**)&hl,  g_hl);
    cudaGetSymbolAddress((void**)&wqh, g_wqh);
    cudaGetSymbolAddress((void**)&wql, g_wql);
    cudaGetSymbolAddress((void**)&wph, g_wph);
    cudaGetSymbolAddress((void**)&wpl, g_wpl);
    cudaGetSymbolAddress((void**)&w1h, g_w1h);
    cudaGetSymbolAddress((void**)&w1l, g_w1l);
    cudaGetSymbolAddress((void**)&w2h, g_w2h);
    cudaGetSymbolAddress((void**)&w2l, g_w2l);

    cudaFuncSetAttribute(hgemm<0, 256, 768>,  cudaFuncAttributeMaxDynamicSharedMemorySize, GSMEM);
    cudaFuncSetAttribute(hgemm<1, 256, 256>,  cudaFuncAttributeMaxDynamicSharedMemorySize, GSMEM);
    cudaFuncSetAttribute(hgemm<2, 256, 1024>, cudaFuncAttributeMaxDynamicSharedMemorySize, GSMEM);
    cudaFuncSetAttribute(hgemm<3, 1024, 256>, cudaFuncAttributeMaxDynamicSharedMemorySize, GSMEM);

    // launch order arranged so the ncu capture window lands on an hgemm,
    // not a wprep (MLP wpreps moved after attention; deps preserved).
    // 0) qkv + proj weight prep
    wprep_kernel<<<768, 256>>>(qkv_w,  wqh, wql, 256, 768);
    wprep_kernel<<<256, 256>>>(proj_w, wph, wpl, 256, 256);
    // 1) LN1 + roll + window partition -> bf16 hi/lo
    ln_kernel<1><<<ROWS / 8, 256>>>(x, ln1_g, ln1_b, ywh, ywl);
    // 2) QKV GEMM (HMMA 256x128 tiles, scatter to q/k/v per-head layout, q scaled)
    hgemm<0, 256, 768><<<dim3(6, ROWS / 256), 256, GSMEM>>>(
        ywh, ywl, wqh, wql, qkv_b, nullptr, qb, kb, vb, nullptr, nullptr);
    // 3) windowed attention -> bf16 hi/lo
    attn_kernel<<<4096 * 8, 256>>>(qb, kb, vb, rpb, owh, owl);
    // 4) proj GEMM + window reverse + un-shift + residual -> x2 (fp32)
    hgemm<1, 256, 256><<<dim3(2, ROWS / 256), 256, GSMEM>>>(
        owh, owl, wph, wpl, proj_b, x, x2, nullptr, nullptr, nullptr, nullptr);
    // 5) MLP weight prep (deferred; must precede hgemm<2>/<3>)
    wprep_kernel<<<1024, 256>>>(mlp_w1, w1h, w1l, 256, 1024);
    wprep_kernel<<<1024, 256>>>(mlp_w2, w2h, w2l, 1024, 256);
    // 6) LN2 -> bf16 hi/lo
    ln_kernel<0><<<ROWS / 8, 256>>>(x2, ln2_g, ln2_b, ywh, ywl);
    // 7) MLP1 + GELU -> bf16 hi/lo hidden
    hgemm<2, 256, 1024><<<dim3(8, ROWS / 256), 256, GSMEM>>>(
        ywh, ywl, w1h, w1l, mlp_b1, nullptr, nullptr, nullptr, nullptr, hh, hl);
    // 8) MLP2 + residual -> out (fp32)
    hgemm<3, 1024, 256><<<dim3(2, ROWS / 256), 256, GSMEM>>>(
        hh, hl, w2h, w2l, mlp_b2, x2, (float*)d_out, nullptr, nullptr, nullptr, nullptr);
    (void)in_sizes; (void)n_in; (void)out_size;
}